// round 13
// baseline (speedup 1.0000x reference)
#include <cuda_runtime.h>
#include <math.h>

#define BQ 8
#define NN 3072
#define HDIM 64
#define KNEI 16
#define BN (BQ*NN)
#define ZSPLIT 2

typedef unsigned long long u64;

// ---- scratch (device globals: allocation-free) ----
__device__ float g_h [BN*HDIM];
__device__ float g_h2[BN*HDIM];
__device__ float g_xx[BN];
__device__ int   g_idx[BN*KNEI];
__device__ float g_A[BN*128];
__device__ float g_C[BN*128];
__device__ __align__(16) float g_d2p[BN*ZSPLIT*KNEI];
__device__ __align__(16) int   g_i2p[BN*ZSPLIT*KNEI];
__device__ float g_pmax[BQ*24*64];

// branchless fast ELU: MUFU.EX2-based, off the fma pipe, no divergence.
__device__ __forceinline__ float elu_f(float v){
    float e = __expf(fminf(v, 0.f)) - 1.f;
    return v > 0.f ? v : e;
}

__device__ __forceinline__ u64 ffma2(u64 a, u64 b, u64 c){
    u64 d; asm("fma.rn.f32x2 %0,%1,%2,%3;" : "=l"(d) : "l"(a), "l"(b), "l"(c)); return d;
}
__device__ __forceinline__ u64 packf2(float lo, float hi){
    u64 r; asm("mov.b64 %0,{%1,%2};" : "=l"(r) : "f"(lo), "f"(hi)); return r;
}
__device__ __forceinline__ float2 unpk(u64 v){
    float2 r; asm("mov.b64 {%0,%1},%2;" : "=f"(r.x), "=f"(r.y) : "l"(v)); return r;
}

// ---------------------------------------------------------------- embed (+ fused ||h||^2)
__global__ void __launch_bounds__(256) k_embed(const float* __restrict__ x, const float* __restrict__ dn,
                        const float* __restrict__ Wi, const float* __restrict__ bi)
{
    __shared__ float part[8];
    int i = blockIdx.x * 256 + threadIdx.x;
    int node = i >> 6, j = i & 63;
    float s = bi[j];
#pragma unroll
    for (int d = 0; d < 3; d++)
        s += x[node*3 + d] * dn[d] * Wi[d*HDIM + j];
    float hv = elu_f(s);
    g_h[i] = hv;
    float sq = hv * hv;
#pragma unroll
    for (int o = 16; o > 0; o >>= 1) sq += __shfl_xor_sync(0xffffffffu, sq, o);
    if ((threadIdx.x & 31) == 0) part[threadIdx.x >> 5] = sq;
    __syncthreads();
    if (threadIdx.x < 4)
        g_xx[blockIdx.x*4 + threadIdx.x] = part[2*threadIdx.x] + part[2*threadIdx.x + 1];
}

// ---------------------------------------------------------------- knn partial (candidate split ZSPLIT-way)
__global__ void __launch_bounds__(128) k_knn(int src)
{
    const float* h = src ? g_h2 : g_h;
    __shared__ __align__(16) float sc[64*64];
    __shared__ float sxx[64];

    int b = blockIdx.y;
    int q = blockIdx.x * 128 + threadIdx.x;
    int zc = blockIdx.z * (NN/ZSPLIT);
    const float* hb = h + (size_t)b*NN*HDIM;

    u64 hq2[32];
    {
        const float4* p = (const float4*)(hb + (size_t)q*HDIM);
#pragma unroll
        for (int t = 0; t < 16; t++) {
            float4 v = p[t];
            hq2[2*t]   = packf2(v.x, v.y);
            hq2[2*t+1] = packf2(v.z, v.w);
        }
    }
    float qxx = g_xx[b*NN + q];

    float dist[KNEI]; int idxs[KNEI];
#pragma unroll
    for (int i = 0; i < KNEI; i++) { dist[i] = 3.0e38f; idxs[i] = 0; }

    for (int c0 = zc; c0 < zc + NN/ZSPLIT; c0 += 64) {
        __syncthreads();
        {
            const float4* s4 = (const float4*)(hb + (size_t)c0*HDIM);
            float4* d4 = (float4*)sc;
#pragma unroll
            for (int t = 0; t < 8; t++) d4[threadIdx.x + 128*t] = s4[threadIdx.x + 128*t];
        }
        if (threadIdx.x < 64) sxx[threadIdx.x] = g_xx[b*NN + c0 + threadIdx.x];
        __syncthreads();

#pragma unroll 1
        for (int c = 0; c < 64; c++) {
            const ulonglong2* cv = (const ulonglong2*)(sc + c*64);
            u64 a0 = 0ull, a1 = 0ull, a2 = 0ull, a3 = 0ull;
#pragma unroll
            for (int t = 0; t < 16; t++) {
                ulonglong2 m = cv[t];
                if (t & 1) { a2 = ffma2(hq2[2*t], m.x, a2); a3 = ffma2(hq2[2*t+1], m.y, a3); }
                else       { a0 = ffma2(hq2[2*t], m.x, a0); a1 = ffma2(hq2[2*t+1], m.y, a1); }
            }
            float2 f0 = unpk(a0), f1 = unpk(a1), f2 = unpk(a2), f3 = unpk(a3);
            float sum = ((f0.x+f0.y)+(f1.x+f1.y)) + ((f2.x+f2.y)+(f3.x+f3.y));
            float d2 = qxx + sxx[c] - 2.f*sum;
            if (d2 < dist[KNEI-1]) {
                int ci = c0 + c;
#pragma unroll
                for (int i = KNEI-1; i >= 0; i--) {
                    if (d2 < dist[i]) {
                        if (i < KNEI-1) { dist[i+1] = dist[i]; idxs[i+1] = idxs[i]; }
                        dist[i] = d2; idxs[i] = ci;
                    }
                }
            }
        }
    }
    size_t o = ((size_t)(b*NN + q)*ZSPLIT + blockIdx.z)*KNEI;
#pragma unroll
    for (int i = 0; i < KNEI; i++) { g_d2p[o+i] = dist[i]; g_i2p[o+i] = idxs[i]; }
}

// ---------------------------------------------------------------- merge ZSPLIT partial top-16 lists
__global__ void k_merge()
{
    int q = blockIdx.x * 256 + threadIdx.x;
    if (q >= BN) return;
    const float4* dp = (const float4*)(g_d2p + (size_t)q*(ZSPLIT*KNEI));
    const int4*   ip = (const int4*)  (g_i2p + (size_t)q*(ZSPLIT*KNEI));
    float dist[KNEI]; int idxs[KNEI];
#pragma unroll
    for (int i = 0; i < KNEI; i++) { dist[i] = 3.0e38f; idxs[i] = 0; }
#pragma unroll 1
    for (int t = 0; t < ZSPLIT*KNEI/4; t++) {
        float4 d4 = dp[t]; int4 i4 = ip[t];
        float dv[4] = {d4.x, d4.y, d4.z, d4.w};
        int   iv[4] = {i4.x, i4.y, i4.z, i4.w};
#pragma unroll
        for (int u = 0; u < 4; u++) {
            float d2 = dv[u];
            if (d2 < dist[KNEI-1]) {
                int ci = iv[u];
#pragma unroll
                for (int i = KNEI-1; i >= 0; i--) {
                    if (d2 < dist[i]) {
                        if (i < KNEI-1) { dist[i+1] = dist[i]; idxs[i+1] = idxs[i]; }
                        dist[i] = d2; idxs[i] = ci;
                    }
                }
            }
        }
    }
    int* op = g_idx + (size_t)q*KNEI;
#pragma unroll
    for (int i = 0; i < KNEI; i++) op[i] = idxs[i];
}

// ---------------------------------------------------------------- per-node A/C precompute
// 2-node register blocking: each thread accumulates nodes nl and nl+8.
__global__ void __launch_bounds__(1024) k_ac(int src, const float* __restrict__ W1l,
                                             const float* __restrict__ b1l)
{
    __shared__ __align__(16) u64 sW[8192];   // [half][d2][j] 64KB
    __shared__ u64 sh[16][32];
    const float* h = src ? g_h2 : g_h;
    int tid = threadIdx.x;

    for (int i = tid; i < 8192; i += 1024) {
        int half = i >> 12;
        int r = i & 4095;
        int d2 = r >> 7, j = r & 127;
        int d = half*64 + 2*d2;
        sW[i] = packf2(W1l[d*128 + j], W1l[(d+1)*128 + j]);
    }
    size_t n0 = (size_t)blockIdx.x * 16;
    if (tid < 512) {
        int nn = tid >> 5, d2 = tid & 31;
        const float* hp = h + (n0 + nn)*HDIM + 2*d2;
        sh[nn][d2] = packf2(hp[0], hp[1]);
    }
    __syncthreads();

    int j = tid & 127, nl = tid >> 7;
    float bj = b1l[j];

    u64 aA = 0ull, cA = 0ull, aB = 0ull, cB = 0ull;
#pragma unroll
    for (int d2 = 0; d2 < 32; d2++) {
        u64 wt = sW[d2*128 + j];
        u64 wb = sW[4096 + d2*128 + j];
        u64 h0 = sh[nl][d2];
        u64 h1 = sh[nl + 8][d2];
        aA = ffma2(h0, wt, aA); cA = ffma2(h0, wb, cA);
        aB = ffma2(h1, wt, aB); cB = ffma2(h1, wb, cB);
    }
    {
        float2 fa = unpk(aA), fc = unpk(cA);
        float c = fc.x + fc.y, a = fa.x + fa.y;
        g_A[(n0 + nl)*128 + j] = a - c + bj;
        g_C[(n0 + nl)*128 + j] = c;
    }
    {
        float2 fa = unpk(aB), fc = unpk(cB);
        float c = fc.x + fc.y, a = fa.x + fa.y;
        g_A[(n0 + nl + 8)*128 + j] = a - c + bj;
        g_C[(n0 + nl + 8)*128 + j] = c;
    }
}

// ---------------------------------------------------------------- edge aggregation
// 256 threads, 8 nodes/block.
// Phase1: warp-per-row coalesced gather; Phase2: warp = node, thread = cols (j, j+32).
__global__ void __launch_bounds__(256) k_edge(int dst, const float* __restrict__ W2l,
                                              const float* __restrict__ b2l)
{
    __shared__ __align__(16) u64 sw[64*64];         // packed W2 [d2][j]  32 KB
    __shared__ __align__(16) float sm1[8][16*128];  // 64 KB
    __shared__ __align__(16) float sA[8][128];      // 4 KB
    __shared__ int snb[8][16];

    int tid = threadIdx.x;
    size_t nodeBase = (size_t)blockIdx.x * 8;
    int b = (int)(nodeBase / NN);

    for (int i = tid; i < 64*64; i += 256) {
        int d2 = i >> 6, jj = i & 63;
        sw[i] = packf2(W2l[(2*d2)*64 + jj], W2l[(2*d2+1)*64 + jj]);
    }
    ((float4*)sA)[tid] = ((const float4*)(g_A + nodeBase*128))[tid];
    if (tid < 128) ((int*)snb)[tid] = g_idx[nodeBase*KNEI + tid];
    __syncthreads();

    // phase 1: 128 (node,k) rows, warp per row, lane = float4 chunk
    {
        int lane = tid & 31, w = tid >> 5;
#pragma unroll 4
        for (int r = w; r < 128; r += 8) {
            int node = r >> 4, k = r & 15;
            const float4* C4 = (const float4*)(g_C + ((size_t)(b*NN + snb[node][k]))*128);
            float4 c = C4[lane];
            float4 a = ((const float4*)&sA[node][0])[lane];
            float4 o;
            o.x = elu_f(a.x + c.x);
            o.y = elu_f(a.y + c.y);
            o.z = elu_f(a.z + c.z);
            o.w = elu_f(a.w + c.w);
            *(float4*)&sm1[node][k*128 + 4*lane] = o;
        }
    }
    __syncthreads();

    // phase 2: warp = node, thread = (j, j+32)
    int w = tid >> 5, j = tid & 31;
    u64 sa[KNEI], sb[KNEI];
#pragma unroll
    for (int k = 0; k < KNEI; k++) { sa[k] = 0ull; sb[k] = 0ull; }

#pragma unroll 1
    for (int g = 0; g < 32; g++) {
        u64 wA0 = sw[(2*g)*64 + j],      wA1 = sw[(2*g+1)*64 + j];
        u64 wB0 = sw[(2*g)*64 + j + 32], wB1 = sw[(2*g+1)*64 + j + 32];
#pragma unroll
        for (int k = 0; k < KNEI; k++) {
            ulonglong2 m = *(const ulonglong2*)&sm1[w][k*128 + 4*g];
            sa[k] = ffma2(m.x, wA0, sa[k]);
            sa[k] = ffma2(m.y, wA1, sa[k]);
            sb[k] = ffma2(m.x, wB0, sb[k]);
            sb[k] = ffma2(m.y, wB1, sb[k]);
        }
    }
    float bbA = b2l[j], bbB = b2l[j + 32];
    float accA = 0.f, accB = 0.f;
#pragma unroll
    for (int k = 0; k < KNEI; k++) {
        float2 fa = unpk(sa[k]); accA += elu_f(fa.x + fa.y + bbA);
        float2 fb = unpk(sb[k]); accB += elu_f(fb.x + fb.y + bbB);
    }

    size_t node = nodeBase + w;
    float* hd = dst ? g_h2 : g_h;
    hd[node*HDIM + j]      = accA;
    hd[node*HDIM + j + 32] = accB;

    float sq = accA*accA + accB*accB;
#pragma unroll
    for (int o = 16; o > 0; o >>= 1) sq += __shfl_xor_sync(0xffffffffu, sq, o);
    if (j == 0) g_xx[node] = sq;
}

// ---------------------------------------------------------------- two-stage maxpool
__global__ void k_pool()
{
    __shared__ float red[256];
    int b = blockIdx.y;
    int n0 = blockIdx.x * 128;
    int tid = threadIdx.x, j = tid & 63, r = tid >> 6;
    const float* h = g_h + ((size_t)b*NN + n0)*HDIM;
    float m = -3.0e38f;
    for (int n = r; n < 128; n += 4) m = fmaxf(m, h[(size_t)n*HDIM + j]);
    red[tid] = m;
    __syncthreads();
    if (tid < 64) {
        float mm = fmaxf(fmaxf(red[tid], red[64+tid]), fmaxf(red[128+tid], red[192+tid]));
        g_pmax[(b*24 + blockIdx.x)*64 + j] = mm;
    }
}

__global__ void k_final(const float* __restrict__ Wo1, const float* __restrict__ bo1,
                        const float* __restrict__ Wo2, const float* __restrict__ bo2,
                        const float* __restrict__ Wo3, const float* __restrict__ bo3,
                        float* __restrict__ out)
{
    __shared__ float pooled[64], o1[64], o2[64];
    int b = blockIdx.x, tid = threadIdx.x;
    float m = -3.0e38f;
#pragma unroll
    for (int p = 0; p < 24; p++) m = fmaxf(m, g_pmax[(b*24 + p)*64 + tid]);
    pooled[tid] = m;
    __syncthreads();
    {
        float s = bo1[tid];
#pragma unroll
        for (int d = 0; d < 64; d++) s += pooled[d] * Wo1[d*64 + tid];
        o1[tid] = elu_f(s);
    }
    __syncthreads();
    {
        float s = bo2[tid];
#pragma unroll
        for (int d = 0; d < 64; d++) s += o1[d] * Wo2[d*64 + tid];
        o2[tid] = elu_f(s);
    }
    __syncthreads();
    if (tid == 0) {
        float s = bo3[0];
#pragma unroll
        for (int d = 0; d < 64; d++) s += o2[d] * Wo3[d];
        out[b] = s;
    }
}

// ---------------------------------------------------------------- host
extern "C" void kernel_launch(void* const* d_in, const int* in_sizes, int n_in,
                              void* d_out, int out_size)
{
    const float* x   = (const float*)d_in[0];
    const float* dn  = (const float*)d_in[1];
    const float* Wi  = (const float*)d_in[2];
    const float* bi  = (const float*)d_in[3];
    const float* W1  = (const float*)d_in[4];
    const float* b1  = (const float*)d_in[5];
    const float* W2  = (const float*)d_in[6];
    const float* b2  = (const float*)d_in[7];
    const float* Wo1 = (const float*)d_in[8];
    const float* bo1 = (const float*)d_in[9];
    const float* Wo2 = (const float*)d_in[10];
    const float* bo2 = (const float*)d_in[11];
    const float* Wo3 = (const float*)d_in[12];
    const float* bo3 = (const float*)d_in[13];
    float* out = (float*)d_out;

    // side stream + events for overlapping k_ac with knn+merge (created once;
    // launch sequence is identical on every call -> deterministic work).
    static cudaStream_t s_ac = nullptr;
    static cudaEvent_t  e_fork[2], e_join[2];
    if (!s_ac) {
        cudaStreamCreateWithFlags(&s_ac, cudaStreamNonBlocking);
        for (int l = 0; l < 2; l++) {
            cudaEventCreateWithFlags(&e_fork[l], cudaEventDisableTiming);
            cudaEventCreateWithFlags(&e_join[l], cudaEventDisableTiming);
        }
    }

    k_embed<<<BN*HDIM/256, 256>>>(x, dn, Wi, bi);

    for (int l = 0; l < 2; l++) {
        int src = l;
        int dst = 1 - l;
        // fork: k_ac only needs h -> run concurrently with knn+merge
        cudaEventRecord(e_fork[l], 0);
        cudaStreamWaitEvent(s_ac, e_fork[l], 0);
        k_ac   <<<BN/16, 1024, 0, s_ac>>>(src, W1 + l*128*128, b1 + l*128);
        cudaEventRecord(e_join[l], s_ac);

        k_knn  <<<dim3(NN/128, BQ, ZSPLIT), 128>>>(src);
        k_merge<<<(BN + 255)/256, 256>>>();

        cudaStreamWaitEvent(0, e_join[l], 0);
        k_edge <<<BN/8, 256>>>(dst, W2 + l*128*64, b2 + l*64);
    }
    k_pool <<<dim3(24, BQ), 256>>>();
    k_final<<<BQ, 64>>>(Wo1, bo1, Wo2, bo2, Wo3, bo3, out);
}

// round 14
// speedup vs baseline: 1.1109x; 1.1109x over previous
#include <cuda_runtime.h>
#include <math.h>

#define BQ 8
#define NN 3072
#define HDIM 64
#define KNEI 16
#define BN (BQ*NN)
#define ZSPLIT 4

typedef unsigned long long u64;

// ---- scratch (device globals: allocation-free) ----
__device__ float g_h [BN*HDIM];
__device__ float g_h2[BN*HDIM];
__device__ float g_xx[BN];
__device__ int   g_idx[BN*KNEI];
__device__ float g_A[BN*128];
__device__ float g_C[BN*128];
__device__ __align__(16) float g_d2p[BN*ZSPLIT*KNEI];
__device__ __align__(16) int   g_i2p[BN*ZSPLIT*KNEI];
__device__ float g_pmax[BQ*24*64];

// branchless fast ELU: MUFU.EX2-based, off the fma pipe, no divergence.
__device__ __forceinline__ float elu_f(float v){
    float e = __expf(fminf(v, 0.f)) - 1.f;
    return v > 0.f ? v : e;
}

__device__ __forceinline__ u64 ffma2(u64 a, u64 b, u64 c){
    u64 d; asm("fma.rn.f32x2 %0,%1,%2,%3;" : "=l"(d) : "l"(a), "l"(b), "l"(c)); return d;
}
__device__ __forceinline__ u64 packf2(float lo, float hi){
    u64 r; asm("mov.b64 %0,{%1,%2};" : "=l"(r) : "f"(lo), "f"(hi)); return r;
}
__device__ __forceinline__ float2 unpk(u64 v){
    float2 r; asm("mov.b64 {%0,%1},%2;" : "=f"(r.x), "=f"(r.y) : "l"(v)); return r;
}

// ---------------------------------------------------------------- embed (+ fused ||h||^2)
__global__ void __launch_bounds__(256) k_embed(const float* __restrict__ x, const float* __restrict__ dn,
                        const float* __restrict__ Wi, const float* __restrict__ bi)
{
    __shared__ float part[8];
    int i = blockIdx.x * 256 + threadIdx.x;
    int node = i >> 6, j = i & 63;
    float s = bi[j];
#pragma unroll
    for (int d = 0; d < 3; d++)
        s += x[node*3 + d] * dn[d] * Wi[d*HDIM + j];
    float hv = elu_f(s);
    g_h[i] = hv;
    float sq = hv * hv;
#pragma unroll
    for (int o = 16; o > 0; o >>= 1) sq += __shfl_xor_sync(0xffffffffu, sq, o);
    if ((threadIdx.x & 31) == 0) part[threadIdx.x >> 5] = sq;
    __syncthreads();
    if (threadIdx.x < 4)
        g_xx[blockIdx.x*4 + threadIdx.x] = part[2*threadIdx.x] + part[2*threadIdx.x + 1];
}

// ---------------------------------------------------------------- knn partial (candidate split ZSPLIT-way)
__global__ void __launch_bounds__(128) k_knn(int src)
{
    const float* h = src ? g_h2 : g_h;
    __shared__ __align__(16) float sc[64*64];
    __shared__ float sxx[64];

    int b = blockIdx.y;
    int q = blockIdx.x * 128 + threadIdx.x;
    int zc = blockIdx.z * (NN/ZSPLIT);
    const float* hb = h + (size_t)b*NN*HDIM;

    u64 hq2[32];
    {
        const float4* p = (const float4*)(hb + (size_t)q*HDIM);
#pragma unroll
        for (int t = 0; t < 16; t++) {
            float4 v = p[t];
            hq2[2*t]   = packf2(v.x, v.y);
            hq2[2*t+1] = packf2(v.z, v.w);
        }
    }
    float qxx = g_xx[b*NN + q];

    float dist[KNEI]; int idxs[KNEI];
#pragma unroll
    for (int i = 0; i < KNEI; i++) { dist[i] = 3.0e38f; idxs[i] = 0; }

    for (int c0 = zc; c0 < zc + NN/ZSPLIT; c0 += 64) {
        __syncthreads();
        {
            const float4* s4 = (const float4*)(hb + (size_t)c0*HDIM);
            float4* d4 = (float4*)sc;
#pragma unroll
            for (int t = 0; t < 8; t++) d4[threadIdx.x + 128*t] = s4[threadIdx.x + 128*t];
        }
        if (threadIdx.x < 64) sxx[threadIdx.x] = g_xx[b*NN + c0 + threadIdx.x];
        __syncthreads();

#pragma unroll 1
        for (int c = 0; c < 64; c++) {
            const ulonglong2* cv = (const ulonglong2*)(sc + c*64);
            u64 a0 = 0ull, a1 = 0ull, a2 = 0ull, a3 = 0ull;
#pragma unroll
            for (int t = 0; t < 16; t++) {
                ulonglong2 m = cv[t];
                if (t & 1) { a2 = ffma2(hq2[2*t], m.x, a2); a3 = ffma2(hq2[2*t+1], m.y, a3); }
                else       { a0 = ffma2(hq2[2*t], m.x, a0); a1 = ffma2(hq2[2*t+1], m.y, a1); }
            }
            float2 f0 = unpk(a0), f1 = unpk(a1), f2 = unpk(a2), f3 = unpk(a3);
            float sum = ((f0.x+f0.y)+(f1.x+f1.y)) + ((f2.x+f2.y)+(f3.x+f3.y));
            float d2 = qxx + sxx[c] - 2.f*sum;
            if (d2 < dist[KNEI-1]) {
                int ci = c0 + c;
#pragma unroll
                for (int i = KNEI-1; i >= 0; i--) {
                    if (d2 < dist[i]) {
                        if (i < KNEI-1) { dist[i+1] = dist[i]; idxs[i+1] = idxs[i]; }
                        dist[i] = d2; idxs[i] = ci;
                    }
                }
            }
        }
    }
    size_t o = ((size_t)(b*NN + q)*ZSPLIT + blockIdx.z)*KNEI;
#pragma unroll
    for (int i = 0; i < KNEI; i++) { g_d2p[o+i] = dist[i]; g_i2p[o+i] = idxs[i]; }
}

// ---------------------------------------------------------------- merge ZSPLIT partial top-16 lists
__global__ void k_merge()
{
    int q = blockIdx.x * 256 + threadIdx.x;
    if (q >= BN) return;
    const float4* dp = (const float4*)(g_d2p + (size_t)q*(ZSPLIT*KNEI));
    const int4*   ip = (const int4*)  (g_i2p + (size_t)q*(ZSPLIT*KNEI));
    float dist[KNEI]; int idxs[KNEI];
#pragma unroll
    for (int i = 0; i < KNEI; i++) { dist[i] = 3.0e38f; idxs[i] = 0; }
#pragma unroll 1
    for (int t = 0; t < ZSPLIT*KNEI/4; t++) {
        float4 d4 = dp[t]; int4 i4 = ip[t];
        float dv[4] = {d4.x, d4.y, d4.z, d4.w};
        int   iv[4] = {i4.x, i4.y, i4.z, i4.w};
#pragma unroll
        for (int u = 0; u < 4; u++) {
            float d2 = dv[u];
            if (d2 < dist[KNEI-1]) {
                int ci = iv[u];
#pragma unroll
                for (int i = KNEI-1; i >= 0; i--) {
                    if (d2 < dist[i]) {
                        if (i < KNEI-1) { dist[i+1] = dist[i]; idxs[i+1] = idxs[i]; }
                        dist[i] = d2; idxs[i] = ci;
                    }
                }
            }
        }
    }
    int* op = g_idx + (size_t)q*KNEI;
#pragma unroll
    for (int i = 0; i < KNEI; i++) op[i] = idxs[i];
}

// ---------------------------------------------------------------- per-node A/C precompute
// 2-node register blocking: each thread accumulates nodes nl and nl+8.
__global__ void __launch_bounds__(1024) k_ac(int src, const float* __restrict__ W1l,
                                             const float* __restrict__ b1l)
{
    __shared__ __align__(16) u64 sW[8192];   // [half][d2][j] 64KB
    __shared__ u64 sh[16][32];
    const float* h = src ? g_h2 : g_h;
    int tid = threadIdx.x;

    for (int i = tid; i < 8192; i += 1024) {
        int half = i >> 12;
        int r = i & 4095;
        int d2 = r >> 7, j = r & 127;
        int d = half*64 + 2*d2;
        sW[i] = packf2(W1l[d*128 + j], W1l[(d+1)*128 + j]);
    }
    size_t n0 = (size_t)blockIdx.x * 16;
    if (tid < 512) {
        int nn = tid >> 5, d2 = tid & 31;
        const float* hp = h + (n0 + nn)*HDIM + 2*d2;
        sh[nn][d2] = packf2(hp[0], hp[1]);
    }
    __syncthreads();

    int j = tid & 127, nl = tid >> 7;
    float bj = b1l[j];

    u64 aA = 0ull, cA = 0ull, aB = 0ull, cB = 0ull;
#pragma unroll
    for (int d2 = 0; d2 < 32; d2++) {
        u64 wt = sW[d2*128 + j];
        u64 wb = sW[4096 + d2*128 + j];
        u64 h0 = sh[nl][d2];
        u64 h1 = sh[nl + 8][d2];
        aA = ffma2(h0, wt, aA); cA = ffma2(h0, wb, cA);
        aB = ffma2(h1, wt, aB); cB = ffma2(h1, wb, cB);
    }
    {
        float2 fa = unpk(aA), fc = unpk(cA);
        float c = fc.x + fc.y, a = fa.x + fa.y;
        g_A[(n0 + nl)*128 + j] = a - c + bj;
        g_C[(n0 + nl)*128 + j] = c;
    }
    {
        float2 fa = unpk(aB), fc = unpk(cB);
        float c = fc.x + fc.y, a = fa.x + fa.y;
        g_A[(n0 + nl + 8)*128 + j] = a - c + bj;
        g_C[(n0 + nl + 8)*128 + j] = c;
    }
}

// ---------------------------------------------------------------- edge aggregation
// 256 threads, 8 nodes/block.
// Phase1: warp-per-row coalesced gather; Phase2: warp = node, thread = cols (j, j+32).
__global__ void __launch_bounds__(256) k_edge(int dst, const float* __restrict__ W2l,
                                              const float* __restrict__ b2l)
{
    __shared__ __align__(16) u64 sw[64*64];         // packed W2 [d2][j]  32 KB
    __shared__ __align__(16) float sm1[8][16*128];  // 64 KB
    __shared__ __align__(16) float sA[8][128];      // 4 KB
    __shared__ int snb[8][16];

    int tid = threadIdx.x;
    size_t nodeBase = (size_t)blockIdx.x * 8;
    int b = (int)(nodeBase / NN);

    for (int i = tid; i < 64*64; i += 256) {
        int d2 = i >> 6, jj = i & 63;
        sw[i] = packf2(W2l[(2*d2)*64 + jj], W2l[(2*d2+1)*64 + jj]);
    }
    ((float4*)sA)[tid] = ((const float4*)(g_A + nodeBase*128))[tid];
    if (tid < 128) ((int*)snb)[tid] = g_idx[nodeBase*KNEI + tid];
    __syncthreads();

    // phase 1: 128 (node,k) rows, warp per row, lane = float4 chunk
    {
        int lane = tid & 31, w = tid >> 5;
#pragma unroll 4
        for (int r = w; r < 128; r += 8) {
            int node = r >> 4, k = r & 15;
            const float4* C4 = (const float4*)(g_C + ((size_t)(b*NN + snb[node][k]))*128);
            float4 c = C4[lane];
            float4 a = ((const float4*)&sA[node][0])[lane];
            float4 o;
            o.x = elu_f(a.x + c.x);
            o.y = elu_f(a.y + c.y);
            o.z = elu_f(a.z + c.z);
            o.w = elu_f(a.w + c.w);
            *(float4*)&sm1[node][k*128 + 4*lane] = o;
        }
    }
    __syncthreads();

    // phase 2: warp = node, thread = (j, j+32)
    int w = tid >> 5, j = tid & 31;
    u64 sa[KNEI], sb[KNEI];
#pragma unroll
    for (int k = 0; k < KNEI; k++) { sa[k] = 0ull; sb[k] = 0ull; }

#pragma unroll 1
    for (int g = 0; g < 32; g++) {
        u64 wA0 = sw[(2*g)*64 + j],      wA1 = sw[(2*g+1)*64 + j];
        u64 wB0 = sw[(2*g)*64 + j + 32], wB1 = sw[(2*g+1)*64 + j + 32];
#pragma unroll
        for (int k = 0; k < KNEI; k++) {
            ulonglong2 m = *(const ulonglong2*)&sm1[w][k*128 + 4*g];
            sa[k] = ffma2(m.x, wA0, sa[k]);
            sa[k] = ffma2(m.y, wA1, sa[k]);
            sb[k] = ffma2(m.x, wB0, sb[k]);
            sb[k] = ffma2(m.y, wB1, sb[k]);
        }
    }
    float bbA = b2l[j], bbB = b2l[j + 32];
    float accA = 0.f, accB = 0.f;
#pragma unroll
    for (int k = 0; k < KNEI; k++) {
        float2 fa = unpk(sa[k]); accA += elu_f(fa.x + fa.y + bbA);
        float2 fb = unpk(sb[k]); accB += elu_f(fb.x + fb.y + bbB);
    }

    size_t node = nodeBase + w;
    float* hd = dst ? g_h2 : g_h;
    hd[node*HDIM + j]      = accA;
    hd[node*HDIM + j + 32] = accB;

    float sq = accA*accA + accB*accB;
#pragma unroll
    for (int o = 16; o > 0; o >>= 1) sq += __shfl_xor_sync(0xffffffffu, sq, o);
    if (j == 0) g_xx[node] = sq;
}

// ---------------------------------------------------------------- two-stage maxpool
__global__ void k_pool()
{
    __shared__ float red[256];
    int b = blockIdx.y;
    int n0 = blockIdx.x * 128;
    int tid = threadIdx.x, j = tid & 63, r = tid >> 6;
    const float* h = g_h + ((size_t)b*NN + n0)*HDIM;
    float m = -3.0e38f;
    for (int n = r; n < 128; n += 4) m = fmaxf(m, h[(size_t)n*HDIM + j]);
    red[tid] = m;
    __syncthreads();
    if (tid < 64) {
        float mm = fmaxf(fmaxf(red[tid], red[64+tid]), fmaxf(red[128+tid], red[192+tid]));
        g_pmax[(b*24 + blockIdx.x)*64 + j] = mm;
    }
}

__global__ void k_final(const float* __restrict__ Wo1, const float* __restrict__ bo1,
                        const float* __restrict__ Wo2, const float* __restrict__ bo2,
                        const float* __restrict__ Wo3, const float* __restrict__ bo3,
                        float* __restrict__ out)
{
    __shared__ float pooled[64], o1[64], o2[64];
    int b = blockIdx.x, tid = threadIdx.x;
    float m = -3.0e38f;
#pragma unroll
    for (int p = 0; p < 24; p++) m = fmaxf(m, g_pmax[(b*24 + p)*64 + tid]);
    pooled[tid] = m;
    __syncthreads();
    {
        float s = bo1[tid];
#pragma unroll
        for (int d = 0; d < 64; d++) s += pooled[d] * Wo1[d*64 + tid];
        o1[tid] = elu_f(s);
    }
    __syncthreads();
    {
        float s = bo2[tid];
#pragma unroll
        for (int d = 0; d < 64; d++) s += o1[d] * Wo2[d*64 + tid];
        o2[tid] = elu_f(s);
    }
    __syncthreads();
    if (tid == 0) {
        float s = bo3[0];
#pragma unroll
        for (int d = 0; d < 64; d++) s += o2[d] * Wo3[d];
        out[b] = s;
    }
}

// ---------------------------------------------------------------- host
extern "C" void kernel_launch(void* const* d_in, const int* in_sizes, int n_in,
                              void* d_out, int out_size)
{
    const float* x   = (const float*)d_in[0];
    const float* dn  = (const float*)d_in[1];
    const float* Wi  = (const float*)d_in[2];
    const float* bi  = (const float*)d_in[3];
    const float* W1  = (const float*)d_in[4];
    const float* b1  = (const float*)d_in[5];
    const float* W2  = (const float*)d_in[6];
    const float* b2  = (const float*)d_in[7];
    const float* Wo1 = (const float*)d_in[8];
    const float* bo1 = (const float*)d_in[9];
    const float* Wo2 = (const float*)d_in[10];
    const float* bo2 = (const float*)d_in[11];
    const float* Wo3 = (const float*)d_in[12];
    const float* bo3 = (const float*)d_in[13];
    float* out = (float*)d_out;

    k_embed<<<BN*HDIM/256, 256>>>(x, dn, Wi, bi);

    for (int l = 0; l < 2; l++) {
        int src = l;
        int dst = 1 - l;
        k_knn  <<<dim3(NN/128, BQ, ZSPLIT), 128>>>(src);
        k_merge<<<(BN + 255)/256, 256>>>();
        k_ac   <<<BN/16, 1024>>>(src, W1 + l*128*128, b1 + l*128);
        k_edge <<<BN/8, 256>>>(dst, W2 + l*128*64, b2 + l*64);
    }
    k_pool <<<dim3(24, BQ), 256>>>();
    k_final<<<BQ, 64>>>(Wo1, bo1, Wo2, bo2, Wo3, bo3, out);
}

// round 16
// speedup vs baseline: 1.2543x; 1.1291x over previous
#include <cuda_runtime.h>
#include <math.h>
#include <stdint.h>

#define BQ 8
#define NN 3072
#define HDIM 64
#define KNEI 16
#define BN (BQ*NN)
#define ZSPLIT 3

typedef unsigned long long u64;

// ---- scratch (device globals: allocation-free) ----
__device__ float g_h [BN*HDIM];
__device__ float g_h2[BN*HDIM];
__device__ float g_xx[BN];
__device__ int   g_idx[BN*KNEI];
__device__ float g_A[BN*128];
__device__ float g_C[BN*128];
__device__ __align__(16) float g_d2p[BN*ZSPLIT*KNEI];
__device__ __align__(16) int   g_i2p[BN*ZSPLIT*KNEI];
__device__ float g_pmax[BQ*24*64];

// branchless fast ELU: MUFU.EX2-based, off the fma pipe, no divergence.
__device__ __forceinline__ float elu_f(float v){
    float e = __expf(fminf(v, 0.f)) - 1.f;
    return v > 0.f ? v : e;
}

__device__ __forceinline__ u64 ffma2(u64 a, u64 b, u64 c){
    u64 d; asm("fma.rn.f32x2 %0,%1,%2,%3;" : "=l"(d) : "l"(a), "l"(b), "l"(c)); return d;
}
__device__ __forceinline__ u64 packf2(float lo, float hi){
    u64 r; asm("mov.b64 %0,{%1,%2};" : "=l"(r) : "f"(lo), "f"(hi)); return r;
}
__device__ __forceinline__ float2 unpk(u64 v){
    float2 r; asm("mov.b64 {%0,%1},%2;" : "=f"(r.x), "=f"(r.y) : "l"(v)); return r;
}
__device__ __forceinline__ void cp16(void* smem, const void* g){
    unsigned int a = (unsigned int)__cvta_generic_to_shared(smem);
    asm volatile("cp.async.cg.shared.global [%0], [%1], 16;" :: "r"(a), "l"(g));
}
__device__ __forceinline__ void cp4(void* smem, const void* g){
    unsigned int a = (unsigned int)__cvta_generic_to_shared(smem);
    asm volatile("cp.async.ca.shared.global [%0], [%1], 4;" :: "r"(a), "l"(g));
}

// ---------------------------------------------------------------- embed (+ fused ||h||^2)
__global__ void __launch_bounds__(256) k_embed(const float* __restrict__ x, const float* __restrict__ dn,
                        const float* __restrict__ Wi, const float* __restrict__ bi)
{
    __shared__ float part[8];
    int i = blockIdx.x * 256 + threadIdx.x;
    int node = i >> 6, j = i & 63;
    float s = bi[j];
#pragma unroll
    for (int d = 0; d < 3; d++)
        s += x[node*3 + d] * dn[d] * Wi[d*HDIM + j];
    float hv = elu_f(s);
    g_h[i] = hv;
    float sq = hv * hv;
#pragma unroll
    for (int o = 16; o > 0; o >>= 1) sq += __shfl_xor_sync(0xffffffffu, sq, o);
    if ((threadIdx.x & 31) == 0) part[threadIdx.x >> 5] = sq;
    __syncthreads();
    if (threadIdx.x < 4)
        g_xx[blockIdx.x*4 + threadIdx.x] = part[2*threadIdx.x] + part[2*threadIdx.x + 1];
}

// ---------------------------------------------------------------- knn partial (candidate split ZSPLIT-way)
// cp.async double-buffered candidate tiles: prefetch t+1 under compute of t.
__global__ void __launch_bounds__(128) k_knn(int src)
{
    const float* h = src ? g_h2 : g_h;
    __shared__ __align__(16) float sc[2][64*64];
    __shared__ float sxx[2][64];

    int b = blockIdx.y;
    int q = blockIdx.x * 128 + threadIdx.x;
    int zc = blockIdx.z * (NN/ZSPLIT);
    const int NT = (NN/ZSPLIT)/64;
    const float* hb = h + (size_t)b*NN*HDIM;

    u64 hq2[32];
    {
        const float4* p = (const float4*)(hb + (size_t)q*HDIM);
#pragma unroll
        for (int t = 0; t < 16; t++) {
            float4 v = p[t];
            hq2[2*t]   = packf2(v.x, v.y);
            hq2[2*t+1] = packf2(v.z, v.w);
        }
    }
    float qxx = g_xx[b*NN + q];

    float dist[KNEI]; int idxs[KNEI];
#pragma unroll
    for (int i = 0; i < KNEI; i++) { dist[i] = 3.0e38f; idxs[i] = 0; }

    // prefetch tile 0
    {
        const float4* s4 = (const float4*)(hb + (size_t)zc*HDIM);
#pragma unroll
        for (int t = 0; t < 8; t++)
            cp16(&((float4*)sc[0])[threadIdx.x + 128*t], &s4[threadIdx.x + 128*t]);
        if (threadIdx.x < 64) cp4(&sxx[0][threadIdx.x], &g_xx[b*NN + zc + threadIdx.x]);
        asm volatile("cp.async.commit_group;" ::: "memory");
    }

#pragma unroll 1
    for (int t = 0; t < NT; t++) {
        int p = t & 1;
        asm volatile("cp.async.wait_group 0;" ::: "memory");
        __syncthreads();
        if (t + 1 < NT) {
            int c1 = zc + (t+1)*64;
            const float4* s4 = (const float4*)(hb + (size_t)c1*HDIM);
#pragma unroll
            for (int u = 0; u < 8; u++)
                cp16(&((float4*)sc[1-p])[threadIdx.x + 128*u], &s4[threadIdx.x + 128*u]);
            if (threadIdx.x < 64) cp4(&sxx[1-p][threadIdx.x], &g_xx[b*NN + c1 + threadIdx.x]);
            asm volatile("cp.async.commit_group;" ::: "memory");
        }
        int c0 = zc + t*64;

#pragma unroll 1
        for (int c = 0; c < 64; c++) {
            const ulonglong2* cv = (const ulonglong2*)(sc[p] + c*64);
            u64 a0 = 0ull, a1 = 0ull, a2 = 0ull, a3 = 0ull;
#pragma unroll
            for (int tt = 0; tt < 16; tt++) {
                ulonglong2 m = cv[tt];
                if (tt & 1) { a2 = ffma2(hq2[2*tt], m.x, a2); a3 = ffma2(hq2[2*tt+1], m.y, a3); }
                else        { a0 = ffma2(hq2[2*tt], m.x, a0); a1 = ffma2(hq2[2*tt+1], m.y, a1); }
            }
            float2 f0 = unpk(a0), f1 = unpk(a1), f2 = unpk(a2), f3 = unpk(a3);
            float sum = ((f0.x+f0.y)+(f1.x+f1.y)) + ((f2.x+f2.y)+(f3.x+f3.y));
            float d2 = qxx + sxx[p][c] - 2.f*sum;
            if (d2 < dist[KNEI-1]) {
                int ci = c0 + c;
#pragma unroll
                for (int i = KNEI-1; i >= 0; i--) {
                    if (d2 < dist[i]) {
                        if (i < KNEI-1) { dist[i+1] = dist[i]; idxs[i+1] = idxs[i]; }
                        dist[i] = d2; idxs[i] = ci;
                    }
                }
            }
        }
        __syncthreads();
    }
    size_t o = ((size_t)(b*NN + q)*ZSPLIT + blockIdx.z)*KNEI;
#pragma unroll
    for (int i = 0; i < KNEI; i++) { g_d2p[o+i] = dist[i]; g_i2p[o+i] = idxs[i]; }
}

// ---------------------------------------------------------------- merge ZSPLIT partial top-16 lists
__global__ void k_merge()
{
    int q = blockIdx.x * 256 + threadIdx.x;
    if (q >= BN) return;
    const float4* dp = (const float4*)(g_d2p + (size_t)q*(ZSPLIT*KNEI));
    const int4*   ip = (const int4*)  (g_i2p + (size_t)q*(ZSPLIT*KNEI));
    float dist[KNEI]; int idxs[KNEI];
#pragma unroll
    for (int i = 0; i < KNEI; i++) { dist[i] = 3.0e38f; idxs[i] = 0; }
#pragma unroll 1
    for (int t = 0; t < ZSPLIT*KNEI/4; t++) {
        float4 d4 = dp[t]; int4 i4 = ip[t];
        float dv[4] = {d4.x, d4.y, d4.z, d4.w};
        int   iv[4] = {i4.x, i4.y, i4.z, i4.w};
#pragma unroll
        for (int u = 0; u < 4; u++) {
            float d2 = dv[u];
            if (d2 < dist[KNEI-1]) {
                int ci = iv[u];
#pragma unroll
                for (int i = KNEI-1; i >= 0; i--) {
                    if (d2 < dist[i]) {
                        if (i < KNEI-1) { dist[i+1] = dist[i]; idxs[i+1] = idxs[i]; }
                        dist[i] = d2; idxs[i] = ci;
                    }
                }
            }
        }
    }
    int* op = g_idx + (size_t)q*KNEI;
#pragma unroll
    for (int i = 0; i < KNEI; i++) op[i] = idxs[i];
}

// ---------------------------------------------------------------- per-node A/C precompute
// 2-node register blocking: each thread accumulates nodes nl and nl+8.
__global__ void __launch_bounds__(1024) k_ac(int src, const float* __restrict__ W1l,
                                             const float* __restrict__ b1l)
{
    __shared__ __align__(16) u64 sW[8192];   // [half][d2][j] 64KB
    __shared__ u64 sh[16][32];
    const float* h = src ? g_h2 : g_h;
    int tid = threadIdx.x;

    for (int i = tid; i < 8192; i += 1024) {
        int half = i >> 12;
        int r = i & 4095;
        int d2 = r >> 7, j = r & 127;
        int d = half*64 + 2*d2;
        sW[i] = packf2(W1l[d*128 + j], W1l[(d+1)*128 + j]);
    }
    size_t n0 = (size_t)blockIdx.x * 16;
    if (tid < 512) {
        int nn = tid >> 5, d2 = tid & 31;
        const float* hp = h + (n0 + nn)*HDIM + 2*d2;
        sh[nn][d2] = packf2(hp[0], hp[1]);
    }
    __syncthreads();

    int j = tid & 127, nl = tid >> 7;
    float bj = b1l[j];

    u64 aA = 0ull, cA = 0ull, aB = 0ull, cB = 0ull;
#pragma unroll
    for (int d2 = 0; d2 < 32; d2++) {
        u64 wt = sW[d2*128 + j];
        u64 wb = sW[4096 + d2*128 + j];
        u64 h0 = sh[nl][d2];
        u64 h1 = sh[nl + 8][d2];
        aA = ffma2(h0, wt, aA); cA = ffma2(h0, wb, cA);
        aB = ffma2(h1, wt, aB); cB = ffma2(h1, wb, cB);
    }
    {
        float2 fa = unpk(aA), fc = unpk(cA);
        float c = fc.x + fc.y, a = fa.x + fa.y;
        g_A[(n0 + nl)*128 + j] = a - c + bj;
        g_C[(n0 + nl)*128 + j] = c;
    }
    {
        float2 fa = unpk(aB), fc = unpk(cB);
        float c = fc.x + fc.y, a = fa.x + fa.y;
        g_A[(n0 + nl + 8)*128 + j] = a - c + bj;
        g_C[(n0 + nl + 8)*128 + j] = c;
    }
}

// ---------------------------------------------------------------- edge aggregation
// 256 threads, 8 nodes/block.
// Phase1: warp-per-row coalesced gather; Phase2: warp = node, thread = cols (j, j+32).
__global__ void __launch_bounds__(256) k_edge(int dst, const float* __restrict__ W2l,
                                              const float* __restrict__ b2l)
{
    __shared__ __align__(16) u64 sw[64*64];         // packed W2 [d2][j]  32 KB
    __shared__ __align__(16) float sm1[8][16*128];  // 64 KB
    __shared__ __align__(16) float sA[8][128];      // 4 KB
    __shared__ int snb[8][16];

    int tid = threadIdx.x;
    size_t nodeBase = (size_t)blockIdx.x * 8;
    int b = (int)(nodeBase / NN);

    for (int i = tid; i < 64*64; i += 256) {
        int d2 = i >> 6, jj = i & 63;
        sw[i] = packf2(W2l[(2*d2)*64 + jj], W2l[(2*d2+1)*64 + jj]);
    }
    ((float4*)sA)[tid] = ((const float4*)(g_A + nodeBase*128))[tid];
    if (tid < 128) ((int*)snb)[tid] = g_idx[nodeBase*KNEI + tid];
    __syncthreads();

    // phase 1: 128 (node,k) rows, warp per row, lane = float4 chunk
    {
        int lane = tid & 31, w = tid >> 5;
#pragma unroll 4
        for (int r = w; r < 128; r += 8) {
            int node = r >> 4, k = r & 15;
            const float4* C4 = (const float4*)(g_C + ((size_t)(b*NN + snb[node][k]))*128);
            float4 c = C4[lane];
            float4 a = ((const float4*)&sA[node][0])[lane];
            float4 o;
            o.x = elu_f(a.x + c.x);
            o.y = elu_f(a.y + c.y);
            o.z = elu_f(a.z + c.z);
            o.w = elu_f(a.w + c.w);
            *(float4*)&sm1[node][k*128 + 4*lane] = o;
        }
    }
    __syncthreads();

    // phase 2: warp = node, thread = (j, j+32)
    int w = tid >> 5, j = tid & 31;
    u64 sa[KNEI], sb[KNEI];
#pragma unroll
    for (int k = 0; k < KNEI; k++) { sa[k] = 0ull; sb[k] = 0ull; }

#pragma unroll 1
    for (int g = 0; g < 32; g++) {
        u64 wA0 = sw[(2*g)*64 + j],      wA1 = sw[(2*g+1)*64 + j];
        u64 wB0 = sw[(2*g)*64 + j + 32], wB1 = sw[(2*g+1)*64 + j + 32];
#pragma unroll
        for (int k = 0; k < KNEI; k++) {
            ulonglong2 m = *(const ulonglong2*)&sm1[w][k*128 + 4*g];
            sa[k] = ffma2(m.x, wA0, sa[k]);
            sa[k] = ffma2(m.y, wA1, sa[k]);
            sb[k] = ffma2(m.x, wB0, sb[k]);
            sb[k] = ffma2(m.y, wB1, sb[k]);
        }
    }
    float bbA = b2l[j], bbB = b2l[j + 32];
    float accA = 0.f, accB = 0.f;
#pragma unroll
    for (int k = 0; k < KNEI; k++) {
        float2 fa = unpk(sa[k]); accA += elu_f(fa.x + fa.y + bbA);
        float2 fb = unpk(sb[k]); accB += elu_f(fb.x + fb.y + bbB);
    }

    size_t node = nodeBase + w;
    float* hd = dst ? g_h2 : g_h;
    hd[node*HDIM + j]      = accA;
    hd[node*HDIM + j + 32] = accB;

    float sq = accA*accA + accB*accB;
#pragma unroll
    for (int o = 16; o > 0; o >>= 1) sq += __shfl_xor_sync(0xffffffffu, sq, o);
    if (j == 0) g_xx[node] = sq;
}

// ---------------------------------------------------------------- two-stage maxpool
__global__ void k_pool()
{
    __shared__ float red[256];
    int b = blockIdx.y;
    int n0 = blockIdx.x * 128;
    int tid = threadIdx.x, j = tid & 63, r = tid >> 6;
    const float* h = g_h + ((size_t)b*NN + n0)*HDIM;
    float m = -3.0e38f;
    for (int n = r; n < 128; n += 4) m = fmaxf(m, h[(size_t)n*HDIM + j]);
    red[tid] = m;
    __syncthreads();
    if (tid < 64) {
        float mm = fmaxf(fmaxf(red[tid], red[64+tid]), fmaxf(red[128+tid], red[192+tid]));
        g_pmax[(b*24 + blockIdx.x)*64 + j] = mm;
    }
}

__global__ void k_final(const float* __restrict__ Wo1, const float* __restrict__ bo1,
                        const float* __restrict__ Wo2, const float* __restrict__ bo2,
                        const float* __restrict__ Wo3, const float* __restrict__ bo3,
                        float* __restrict__ out)
{
    __shared__ float pooled[64], o1[64], o2[64];
    int b = blockIdx.x, tid = threadIdx.x;
    float m = -3.0e38f;
#pragma unroll
    for (int p = 0; p < 24; p++) m = fmaxf(m, g_pmax[(b*24 + p)*64 + tid]);
    pooled[tid] = m;
    __syncthreads();
    {
        float s = bo1[tid];
#pragma unroll
        for (int d = 0; d < 64; d++) s += pooled[d] * Wo1[d*64 + tid];
        o1[tid] = elu_f(s);
    }
    __syncthreads();
    {
        float s = bo2[tid];
#pragma unroll
        for (int d = 0; d < 64; d++) s += o1[d] * Wo2[d*64 + tid];
        o2[tid] = elu_f(s);
    }
    __syncthreads();
    if (tid == 0) {
        float s = bo3[0];
#pragma unroll
        for (int d = 0; d < 64; d++) s += o2[d] * Wo3[d];
        out[b] = s;
    }
}

// ---------------------------------------------------------------- host
extern "C" void kernel_launch(void* const* d_in, const int* in_sizes, int n_in,
                              void* d_out, int out_size)
{
    const float* x   = (const float*)d_in[0];
    const float* dn  = (const float*)d_in[1];
    const float* Wi  = (const float*)d_in[2];
    const float* bi  = (const float*)d_in[3];
    const float* W1  = (const float*)d_in[4];
    const float* b1  = (const float*)d_in[5];
    const float* W2  = (const float*)d_in[6];
    const float* b2  = (const float*)d_in[7];
    const float* Wo1 = (const float*)d_in[8];
    const float* bo1 = (const float*)d_in[9];
    const float* Wo2 = (const float*)d_in[10];
    const float* bo2 = (const float*)d_in[11];
    const float* Wo3 = (const float*)d_in[12];
    const float* bo3 = (const float*)d_in[13];
    float* out = (float*)d_out;

    k_embed<<<BN*HDIM/256, 256>>>(x, dn, Wi, bi);

    for (int l = 0; l < 2; l++) {
        int src = l;
        int dst = 1 - l;
        k_knn  <<<dim3(NN/128, BQ, ZSPLIT), 128>>>(src);
        k_merge<<<(BN + 255)/256, 256>>>();
        k_ac   <<<BN/16, 1024>>>(src, W1 + l*128*128, b1 + l*128);
        k_edge <<<BN/8, 256>>>(dst, W2 + l*128*64, b2 + l*64);
    }
    k_pool <<<dim3(24, BQ), 256>>>();
    k_final<<<BQ, 64>>>(Wo1, bo1, Wo2, bo2, Wo3, bo3, out);
}